// round 14
// baseline (speedup 1.0000x reference)
#include <cuda_runtime.h>
#include <cuda_fp16.h>
#include <cstdint>

// EdgeNetwork as warp-level HMMA GEMM (mma.sync.m16n8k16):
//   msg[e,i] = sum_{K=0..271} C[e,K] * W[K,i],  K = k*16+j
//   C[e,K]   = b'[e,k] * A[nb_e, j],  b' = [b[e], 1.0]  (k=16 row folds bias)
//   W[k*16+j, i] = Kmat[k, i*16+j]  (k<16),  bias[i*16+j] (k=16)
// Warp = 2 interleaved 16-edge tiles. Per k-step: ONE LDS.128 delivers all 4
// B-fragments (lane-indexed packed layout); bond coeffs come from duplicated
// half2 registers via one shfl each (no smem staging).

#define NW 8                  // warps per CTA
#define EPC (NW * 32)         // 256 edges per CTA

// packed W fragments: g_Wu4[s*32 + lane] = {b00, b01, b10, b11} for (g,t)
__device__ uint4 g_Wu4[17 * 32];

__device__ __forceinline__ void red_add_v2(float* addr, float x, float y) {
    asm volatile("red.global.add.v2.f32 [%0], {%1,%2};"
                 :: "l"(addr), "f"(x), "f"(y) : "memory");
}

__device__ __forceinline__ unsigned hmul2u(__half2 a, __half2 b) {
    __half2 r = __hmul2(a, b);
    return *reinterpret_cast<unsigned*>(&r);
}

__device__ __forceinline__ void mma16816(float& d0, float& d1, float& d2,
                                         float& d3, unsigned a0, unsigned a1,
                                         unsigned a2, unsigned a3,
                                         unsigned b0, unsigned b1) {
    asm volatile(
        "mma.sync.aligned.m16n8k16.row.col.f32.f16.f16.f32 "
        "{%0,%1,%2,%3}, {%4,%5,%6,%7}, {%8,%9}, {%0,%1,%2,%3};"
        : "+f"(d0), "+f"(d1), "+f"(d2), "+f"(d3)
        : "r"(a0), "r"(a1), "r"(a2), "r"(a3), "r"(b0), "r"(b1));
}

// ---------------- setup: zero output; block 0 builds packed W fragments -----
__global__ void build_w_zero(const float* __restrict__ Kmat,
                             const float* __restrict__ bias,
                             float* __restrict__ out, int n_out4) {
    const int gid = blockIdx.x * blockDim.x + threadIdx.x;
    if (gid < n_out4)
        reinterpret_cast<float4*>(out)[gid] = make_float4(0.f, 0.f, 0.f, 0.f);
    if (blockIdx.x == 0) {
        const int tid = threadIdx.x;  // 256
        for (int idx = tid; idx < 17 * 32; idx += 256) {
            const int s = idx >> 5;
            const int l = idx & 31;
            const int g = l >> 2;
            const int t = l & 3;
            // WT[K][n] with K = s*16 + c: = Kmat[s][n*16+c] (s<16) else bias
            auto wt = [&](int n, int c) -> float {
                return (s < 16) ? Kmat[s * 256 + n * 16 + c]
                                : bias[n * 16 + c];
            };
            __half2 x = __floats2half2_rn(wt(g,     2*t),     wt(g,     2*t + 1));
            __half2 y = __floats2half2_rn(wt(g,     2*t + 8), wt(g,     2*t + 9));
            __half2 z = __floats2half2_rn(wt(g + 8, 2*t),     wt(g + 8, 2*t + 1));
            __half2 ww = __floats2half2_rn(wt(g + 8, 2*t + 8), wt(g + 8, 2*t + 9));
            uint4 v;
            v.x = *reinterpret_cast<unsigned*>(&x);
            v.y = *reinterpret_cast<unsigned*>(&y);
            v.z = *reinterpret_cast<unsigned*>(&z);
            v.w = *reinterpret_cast<unsigned*>(&ww);
            g_Wu4[idx] = v;
        }
    }
}

// ---------------- main edge kernel -------------------------------------------
template<bool GUARD>
__global__ void __launch_bounds__(NW * 32)
edge_hmma(const float* __restrict__ bond,
          const int* __restrict__ pairs,
          const float* __restrict__ A,
          float* __restrict__ out,
          int n_edges) {
    __shared__ uint4 Wsm4[17 * 32];     // 8704 B, lane-indexed: [s*32 + lane]

    const int tid = threadIdx.x;
    const int lane = tid & 31;
    const int w = tid >> 5;
    const int g = lane >> 2;      // fragment row group (0..7)
    const int t = lane & 3;       // fragment quad (0..3)

    // stage packed W fragments (verbatim uint4 copy)
    for (int i = tid; i < 17 * 32; i += NW * 32) Wsm4[i] = g_Wu4[i];
    __syncthreads();

    const int warp_base = blockIdx.x * EPC + w * 32;

    // ---- bond prep: lane holds half-row of one edge as 8 DUPLICATED half2 --
    // pass p covers tile p's 16 edges: lane l -> edge p*16 + (l>>1), half l&1
    unsigned hb[2][8];
    #pragma unroll
    for (int p = 0; p < 2; ++p) {
        int er = warp_base + p * 16 + (lane >> 1);
        if (GUARD) er = min(er, n_edges - 1);
        const float4* b4 = reinterpret_cast<const float4*>(bond)
                         + (size_t)er * 4 + (lane & 1) * 2;
        const float4 f0 = b4[0];
        const float4 f1 = b4[1];
        const float bf[8] = {f0.x, f0.y, f0.z, f0.w, f1.x, f1.y, f1.z, f1.w};
        #pragma unroll
        for (int c = 0; c < 8; ++c) {
            __half2 h = __float2half2_rn(bf[c]);    // duplicated pair
            hb[p][c] = *reinterpret_cast<unsigned*>(&h);
        }
    }

    // ---- pairs + A fragments for both tiles ----
    int dst0[2], dst1[2];
    __half2 hal0[2], hah0[2], hal1[2], hah1[2];
    #pragma unroll
    for (int tl = 0; tl < 2; ++tl) {
        const int ebase = warp_base + tl * 16;
        int e0 = ebase + g;
        int e1 = ebase + g + 8;
        if (GUARD) { e0 = min(e0, n_edges - 1); e1 = min(e1, n_edges - 1); }
        const int2 p0 = reinterpret_cast<const int2*>(pairs)[e0];
        const int2 p1 = reinterpret_cast<const int2*>(pairs)[e1];
        dst0[tl] = p0.x;
        dst1[tl] = p1.x;
        const float* A0 = A + (size_t)p0.y * 16;
        const float* A1 = A + (size_t)p1.y * 16;
        const float2 al0 = *reinterpret_cast<const float2*>(A0 + 2 * t);
        const float2 ah0 = *reinterpret_cast<const float2*>(A0 + 8 + 2 * t);
        const float2 al1 = *reinterpret_cast<const float2*>(A1 + 2 * t);
        const float2 ah1 = *reinterpret_cast<const float2*>(A1 + 8 + 2 * t);
        hal0[tl] = __floats2half2_rn(al0.x, al0.y);
        hah0[tl] = __floats2half2_rn(ah0.x, ah0.y);
        hal1[tl] = __floats2half2_rn(al1.x, al1.y);
        hah1[tl] = __floats2half2_rn(ah1.x, ah1.y);
    }

    float d[2][8];
    #pragma unroll
    for (int tl = 0; tl < 2; ++tl)
        #pragma unroll
        for (int q = 0; q < 8; ++q) d[tl][q] = 0.f;

    #pragma unroll
    for (int s = 0; s < 17; ++s) {
        // ONE LDS.128: all 4 B-fragments for this lane, conflict-free phases
        const uint4 wv = Wsm4[s * 32 + lane];

        #pragma unroll
        for (int tl = 0; tl < 2; ++tl) {
            unsigned ul, uh;
            if (s < 16) {
                // b[e][s]: src lane = 2*(local edge) + (s>>3), reg = s&7
                ul = __shfl_sync(0xffffffffu, hb[tl][s & 7],
                                 2 * g + (s >> 3), 32);
                uh = __shfl_sync(0xffffffffu, hb[tl][s & 7],
                                 2 * g + 16 + (s >> 3), 32);
            } else {
                ul = uh = 0x3C003C00u;   // (1.0h, 1.0h) — bias row
            }
            const __half2 bl = *reinterpret_cast<const __half2*>(&ul);
            const __half2 bh = *reinterpret_cast<const __half2*>(&uh);

            const unsigned a0 = hmul2u(bl, hal0[tl]);
            const unsigned a1 = hmul2u(bh, hal1[tl]);
            const unsigned a2 = hmul2u(bl, hah0[tl]);
            const unsigned a3 = hmul2u(bh, hah1[tl]);

            mma16816(d[tl][0], d[tl][1], d[tl][2], d[tl][3],
                     a0, a1, a2, a3, wv.x, wv.y);
            mma16816(d[tl][4], d[tl][5], d[tl][6], d[tl][7],
                     a0, a1, a2, a3, wv.z, wv.w);
        }
    }

    // ---- epilogue ----
    #pragma unroll
    for (int tl = 0; tl < 2; ++tl) {
        const int ebase = warp_base + tl * 16;
        const int e0 = ebase + g;
        const int e1 = ebase + g + 8;
        if (!GUARD || e0 < n_edges) {
            float* o = out + (size_t)dst0[tl] * 16;
            red_add_v2(o + 2 * t, d[tl][0], d[tl][1]);
            red_add_v2(o + 8 + 2 * t, d[tl][4], d[tl][5]);
        }
        if (!GUARD || e1 < n_edges) {
            float* o = out + (size_t)dst1[tl] * 16;
            red_add_v2(o + 2 * t, d[tl][2], d[tl][3]);
            red_add_v2(o + 8 + 2 * t, d[tl][6], d[tl][7]);
        }
    }
}

extern "C" void kernel_launch(void* const* d_in, const int* in_sizes, int n_in,
                              void* d_out, int out_size) {
    const float* A     = (const float*)d_in[0];  // atom_features [n_atoms,16]
    const float* bond  = (const float*)d_in[1];  // bond_features [n_edges,16]
    const int*   pairs = (const int*)  d_in[2];  // pair_indices  [n_edges,2]
    const float* Kmat  = (const float*)d_in[3];  // kernel [16,256]
    const float* bias  = (const float*)d_in[4];  // bias [256]
    float* out = (float*)d_out;                  // [n_atoms,16]

    const int n_edges = in_sizes[2] / 2;
    const int n_out4 = out_size / 4;

    // one launch: zero out[] everywhere; block 0 also builds W fragments
    build_w_zero<<<(n_out4 + 255) / 256, 256>>>(Kmat, bias, out, n_out4);

    if (n_edges % EPC == 0) {
        edge_hmma<false><<<n_edges / EPC, NW * 32>>>(bond, pairs, A, out, n_edges);
    } else {
        const int blocks = (n_edges + EPC - 1) / EPC;
        edge_hmma<true><<<blocks, NW * 32>>>(bond, pairs, A, out, n_edges);
    }
}

// round 15
// speedup vs baseline: 1.4823x; 1.4823x over previous
#include <cuda_runtime.h>
#include <cuda_fp16.h>
#include <cstdint>

// EdgeNetwork as warp-level HMMA GEMM (mma.sync.m16n8k16):
//   msg[e,i] = sum_{K=0..271} C[e,K] * W[K,i],  K = k*16+j
//   C[e,K]   = b'[e,k] * A[nb_e, j],  b' = [b[e], 1.0]  (k=16 row folds bias)
//   W[k*16+j, i] = Kmat[k, i*16+j]  (k<16),  bias[i*16+j] (k=16)
// Warp = 2 interleaved 16-edge tiles. Per k-step: ONE LDS.128 delivers all 4
// B-fragments (lane-indexed packed uint4), bond coeffs via 2 LDS.32 from a
// per-warp smem staging buffer (R13 scheme). 3 MIO ops/step total.

#define NW 8                  // warps per CTA
#define EPC (NW * 32)         // 256 edges per CTA

// packed W fragments: g_Wu4[s*32 + lane] = {b00, b01, b10, b11} for (g,t)
__device__ uint4 g_Wu4[17 * 32];

__device__ __forceinline__ void red_add_v2(float* addr, float x, float y) {
    asm volatile("red.global.add.v2.f32 [%0], {%1,%2};"
                 :: "l"(addr), "f"(x), "f"(y) : "memory");
}

__device__ __forceinline__ unsigned hmul2u(__half2 a, __half2 b) {
    __half2 r = __hmul2(a, b);
    return *reinterpret_cast<unsigned*>(&r);
}

__device__ __forceinline__ void mma16816(float& d0, float& d1, float& d2,
                                         float& d3, unsigned a0, unsigned a1,
                                         unsigned a2, unsigned a3,
                                         unsigned b0, unsigned b1) {
    asm volatile(
        "mma.sync.aligned.m16n8k16.row.col.f32.f16.f16.f32 "
        "{%0,%1,%2,%3}, {%4,%5,%6,%7}, {%8,%9}, {%0,%1,%2,%3};"
        : "+f"(d0), "+f"(d1), "+f"(d2), "+f"(d3)
        : "r"(a0), "r"(a1), "r"(a2), "r"(a3), "r"(b0), "r"(b1));
}

// ---------------- setup: zero output; block 0 builds packed W fragments -----
__global__ void build_w_zero(const float* __restrict__ Kmat,
                             const float* __restrict__ bias,
                             float* __restrict__ out, int n_out4) {
    const int gid = blockIdx.x * blockDim.x + threadIdx.x;
    if (gid < n_out4)
        reinterpret_cast<float4*>(out)[gid] = make_float4(0.f, 0.f, 0.f, 0.f);
    if (blockIdx.x == 0) {
        const int tid = threadIdx.x;  // 256
        for (int idx = tid; idx < 17 * 32; idx += 256) {
            const int s = idx >> 5;
            const int l = idx & 31;
            const int g = l >> 2;
            const int t = l & 3;
            // WT[K][n] with K = s*16 + c: = Kmat[s][n*16+c] (s<16) else bias
            auto wt = [&](int n, int c) -> float {
                return (s < 16) ? Kmat[s * 256 + n * 16 + c]
                                : bias[n * 16 + c];
            };
            __half2 x = __floats2half2_rn(wt(g,     2*t),     wt(g,     2*t + 1));
            __half2 y = __floats2half2_rn(wt(g,     2*t + 8), wt(g,     2*t + 9));
            __half2 z = __floats2half2_rn(wt(g + 8, 2*t),     wt(g + 8, 2*t + 1));
            __half2 ww = __floats2half2_rn(wt(g + 8, 2*t + 8), wt(g + 8, 2*t + 9));
            uint4 v;
            v.x = *reinterpret_cast<unsigned*>(&x);
            v.y = *reinterpret_cast<unsigned*>(&y);
            v.z = *reinterpret_cast<unsigned*>(&z);
            v.w = *reinterpret_cast<unsigned*>(&ww);
            g_Wu4[idx] = v;
        }
    }
}

// ---------------- main edge kernel -------------------------------------------
__global__ void __launch_bounds__(NW * 32)
edge_hmma(const float* __restrict__ bond,
          const int* __restrict__ pairs,
          const float* __restrict__ A,
          float* __restrict__ out,
          int n_edges) {
    __shared__ uint4 Wsm4[17 * 32];             // 8704 B, [s*32 + lane]
    __shared__ __half2 bbuf[NW][2][16][8];      // 8 KB

    const int tid = threadIdx.x;
    const int lane = tid & 31;
    const int w = tid >> 5;
    const int g = lane >> 2;      // fragment row group (0..7)
    const int t = lane & 3;       // fragment quad (0..3)

    // stage packed W fragments (verbatim uint4 copy)
    for (int i = tid; i < 17 * 32; i += NW * 32) Wsm4[i] = g_Wu4[i];
    __syncthreads();

    const int warp_base = blockIdx.x * EPC + w * 32;

    // ---- stage bond rows for both tiles (R13 scheme) ----
    #pragma unroll
    for (int tl = 0; tl < 2; ++tl) {
        const int ebase = warp_base + tl * 16;
        const int et = lane >> 1;
        const int hcol = lane & 1;          // 0 -> s 0..7, 1 -> s 8..15
        const int esrc = min(ebase + et, n_edges - 1);
        const float4* b4 = reinterpret_cast<const float4*>(bond)
                         + (size_t)esrc * 4 + hcol * 2;
        const float4 f0 = b4[0];
        const float4 f1 = b4[1];
        float bf[8] = {f0.x, f0.y, f0.z, f0.w, f1.x, f1.y, f1.z, f1.w};
        __half* bb = reinterpret_cast<__half*>(bbuf[w][tl]);
        const int r = et & 7;
        const int hi = et >> 3;
        #pragma unroll
        for (int c = 0; c < 8; ++c) {
            const int s = hcol * 8 + c;
            bb[(s * 8 + r) * 2 + hi] = __float2half_rn(bf[c]);
        }
    }
    __syncwarp();

    // ---- per-thread edges / A fragments for both tiles ----
    int dst0[2], dst1[2];
    __half2 hal0[2], hah0[2], hal1[2], hah1[2];
    #pragma unroll
    for (int tl = 0; tl < 2; ++tl) {
        const int ebase = warp_base + tl * 16;
        const int e0 = min(ebase + g, n_edges - 1);
        const int e1 = min(ebase + g + 8, n_edges - 1);
        const int2 p0 = reinterpret_cast<const int2*>(pairs)[e0];
        const int2 p1 = reinterpret_cast<const int2*>(pairs)[e1];
        dst0[tl] = p0.x;
        dst1[tl] = p1.x;
        const float* A0 = A + (size_t)p0.y * 16;
        const float* A1 = A + (size_t)p1.y * 16;
        const float2 al0 = *reinterpret_cast<const float2*>(A0 + 2 * t);
        const float2 ah0 = *reinterpret_cast<const float2*>(A0 + 8 + 2 * t);
        const float2 al1 = *reinterpret_cast<const float2*>(A1 + 2 * t);
        const float2 ah1 = *reinterpret_cast<const float2*>(A1 + 8 + 2 * t);
        hal0[tl] = __floats2half2_rn(al0.x, al0.y);
        hah0[tl] = __floats2half2_rn(ah0.x, ah0.y);
        hal1[tl] = __floats2half2_rn(al1.x, al1.y);
        hah1[tl] = __floats2half2_rn(ah1.x, ah1.y);
    }

    float d[2][8];
    #pragma unroll
    for (int tl = 0; tl < 2; ++tl)
        #pragma unroll
        for (int q = 0; q < 8; ++q) d[tl][q] = 0.f;

    #pragma unroll
    for (int s = 0; s < 17; ++s) {
        // ONE LDS.128: all 4 B-fragments for this lane (conflict-free phases)
        const uint4 wv = Wsm4[s * 32 + lane];

        #pragma unroll
        for (int tl = 0; tl < 2; ++tl) {
            __half2 bl, bh;
            if (s < 16) {
                const __half2 b2 = bbuf[w][tl][s][g];  // (b[e0][s], b[e1][s])
                bl = __half2half2(__low2half(b2));
                bh = __half2half2(__high2half(b2));
            } else {
                bl = __floats2half2_rn(1.f, 1.f);      // bias row
                bh = bl;
            }
            const unsigned a0 = hmul2u(bl, hal0[tl]);
            const unsigned a1 = hmul2u(bh, hal1[tl]);
            const unsigned a2 = hmul2u(bl, hah0[tl]);
            const unsigned a3 = hmul2u(bh, hah1[tl]);

            mma16816(d[tl][0], d[tl][1], d[tl][2], d[tl][3],
                     a0, a1, a2, a3, wv.x, wv.y);
            mma16816(d[tl][4], d[tl][5], d[tl][6], d[tl][7],
                     a0, a1, a2, a3, wv.z, wv.w);
        }
    }

    // ---- epilogue ----
    #pragma unroll
    for (int tl = 0; tl < 2; ++tl) {
        const int ebase = warp_base + tl * 16;
        const int e0 = ebase + g;
        const int e1 = ebase + g + 8;
        if (e0 < n_edges) {
            float* o = out + (size_t)dst0[tl] * 16;
            red_add_v2(o + 2 * t, d[tl][0], d[tl][1]);
            red_add_v2(o + 8 + 2 * t, d[tl][4], d[tl][5]);
        }
        if (e1 < n_edges) {
            float* o = out + (size_t)dst1[tl] * 16;
            red_add_v2(o + 2 * t, d[tl][2], d[tl][3]);
            red_add_v2(o + 8 + 2 * t, d[tl][6], d[tl][7]);
        }
    }
}

extern "C" void kernel_launch(void* const* d_in, const int* in_sizes, int n_in,
                              void* d_out, int out_size) {
    const float* A     = (const float*)d_in[0];  // atom_features [n_atoms,16]
    const float* bond  = (const float*)d_in[1];  // bond_features [n_edges,16]
    const int*   pairs = (const int*)  d_in[2];  // pair_indices  [n_edges,2]
    const float* Kmat  = (const float*)d_in[3];  // kernel [16,256]
    const float* bias  = (const float*)d_in[4];  // bias [256]
    float* out = (float*)d_out;                  // [n_atoms,16]

    const int n_edges = in_sizes[2] / 2;
    const int n_out4 = out_size / 4;

    // one launch: zero out[] everywhere; block 0 also builds W fragments
    build_w_zero<<<(n_out4 + 255) / 256, 256>>>(Kmat, bias, out, n_out4);

    const int blocks = (n_edges + EPC - 1) / EPC;
    edge_hmma<<<blocks, NW * 32>>>(bond, pairs, A, out, n_edges);
}

// round 16
// speedup vs baseline: 1.6564x; 1.1174x over previous
#include <cuda_runtime.h>
#include <cuda_fp16.h>
#include <cstdint>

// EdgeNetwork as warp-level HMMA GEMM (mma.sync.m16n8k16):
//   msg[e,i] = sum_{K} C[e,K] * W[K,i],  K = k*16+j (272 total, 17 steps)
//   C[e, s*16+j] = b'[e,s] * A[nb_e, j],  b' = [b[e], 1.0]
// K-inner permutation sigma: mma k-position p -> physical j, chosen so that
// thread t owns j in {4t..4t+3}:
//   p=2t -> 4t, p=2t+1 -> 4t+1, p=2t+8 -> 4t+2, p=2t+9 -> 4t+3.
// A is pre-converted to fp16 (same __float2half_rn as before -> numerics
// identical); a row-fragment is ONE uint2 (8B) load per edge row.
// Per k-step: 1 LDS.128 (packed W fragments) + 2 LDS.32 (bond staging).

#define MAX_ATOMS 20000
#define NW 8                  // warps per CTA
#define EPC (NW * 32)         // 256 edges per CTA

__device__ uint4  g_Wu4[17 * 32];          // packed W frags [s*32 + lane]
__device__ __half g_Ah[MAX_ATOMS * 16];    // fp16 atom features

__device__ __forceinline__ void red_add_v2(float* addr, float x, float y) {
    asm volatile("red.global.add.v2.f32 [%0], {%1,%2};"
                 :: "l"(addr), "f"(x), "f"(y) : "memory");
}

__device__ __forceinline__ unsigned hmul2u(__half2 a, __half2 b) {
    __half2 r = __hmul2(a, b);
    return *reinterpret_cast<unsigned*>(&r);
}

__device__ __forceinline__ void mma16816(float& d0, float& d1, float& d2,
                                         float& d3, unsigned a0, unsigned a1,
                                         unsigned a2, unsigned a3,
                                         unsigned b0, unsigned b1) {
    asm volatile(
        "mma.sync.aligned.m16n8k16.row.col.f32.f16.f16.f32 "
        "{%0,%1,%2,%3}, {%4,%5,%6,%7}, {%8,%9}, {%0,%1,%2,%3};"
        : "+f"(d0), "+f"(d1), "+f"(d2), "+f"(d3)
        : "r"(a0), "r"(a1), "r"(a2), "r"(a3), "r"(b0), "r"(b1));
}

// ------- setup: zero out, convert A->fp16, block 0 builds permuted W frags --
__global__ void setup_kernel(const float* __restrict__ A,
                             const float* __restrict__ Kmat,
                             const float* __restrict__ bias,
                             float* __restrict__ out,
                             int n_out4, int n_ah8) {
    const int gid = blockIdx.x * blockDim.x + threadIdx.x;
    if (gid < n_out4)
        reinterpret_cast<float4*>(out)[gid] = make_float4(0.f, 0.f, 0.f, 0.f);

    if (gid < n_ah8) {   // convert 8 floats -> 8 halfs (one uint4 store)
        const float4 f0 = reinterpret_cast<const float4*>(A)[gid * 2];
        const float4 f1 = reinterpret_cast<const float4*>(A)[gid * 2 + 1];
        __half2 h0 = __floats2half2_rn(f0.x, f0.y);
        __half2 h1 = __floats2half2_rn(f0.z, f0.w);
        __half2 h2 = __floats2half2_rn(f1.x, f1.y);
        __half2 h3 = __floats2half2_rn(f1.z, f1.w);
        uint4 v;
        v.x = *reinterpret_cast<unsigned*>(&h0);
        v.y = *reinterpret_cast<unsigned*>(&h1);
        v.z = *reinterpret_cast<unsigned*>(&h2);
        v.w = *reinterpret_cast<unsigned*>(&h3);
        reinterpret_cast<uint4*>(g_Ah)[gid] = v;
    }

    if (blockIdx.x == 0) {
        const int tid = threadIdx.x;  // 256
        for (int idx = tid; idx < 17 * 32; idx += 256) {
            const int s = idx >> 5;
            const int l = idx & 31;
            const int g = l >> 2;
            const int t = l & 3;
            // WT[s*16 + j][n]: = Kmat[s][n*16+j] (s<16) else bias[n*16+j]
            auto wt = [&](int n, int j) -> float {
                return (s < 16) ? Kmat[s * 256 + n * 16 + j]
                                : bias[n * 16 + j];
            };
            // sigma: thread t's mma k-positions map to j = 4t..4t+3
            __half2 x  = __floats2half2_rn(wt(g,     4*t),     wt(g,     4*t + 1));
            __half2 y  = __floats2half2_rn(wt(g,     4*t + 2), wt(g,     4*t + 3));
            __half2 z  = __floats2half2_rn(wt(g + 8, 4*t),     wt(g + 8, 4*t + 1));
            __half2 ww = __floats2half2_rn(wt(g + 8, 4*t + 2), wt(g + 8, 4*t + 3));
            uint4 v;
            v.x = *reinterpret_cast<unsigned*>(&x);
            v.y = *reinterpret_cast<unsigned*>(&y);
            v.z = *reinterpret_cast<unsigned*>(&z);
            v.w = *reinterpret_cast<unsigned*>(&ww);
            g_Wu4[idx] = v;
        }
    }
}

// ---------------- main edge kernel -------------------------------------------
__global__ void __launch_bounds__(NW * 32)
edge_hmma(const float* __restrict__ bond,
          const int* __restrict__ pairs,
          float* __restrict__ out,
          int n_edges) {
    __shared__ uint4 Wsm4[17 * 32];             // 8704 B, [s*32 + lane]
    __shared__ __half2 bbuf[NW][2][16][8];      // 8 KB

    const int tid = threadIdx.x;
    const int lane = tid & 31;
    const int w = tid >> 5;
    const int g = lane >> 2;      // fragment row group (0..7)
    const int t = lane & 3;       // fragment quad (0..3)

    // stage packed W fragments (verbatim uint4 copy)
    for (int i = tid; i < 17 * 32; i += NW * 32) Wsm4[i] = g_Wu4[i];
    __syncthreads();

    const int warp_base = blockIdx.x * EPC + w * 32;

    // ---- stage bond rows for both tiles ----
    #pragma unroll
    for (int tl = 0; tl < 2; ++tl) {
        const int ebase = warp_base + tl * 16;
        const int et = lane >> 1;
        const int hcol = lane & 1;          // 0 -> s 0..7, 1 -> s 8..15
        const int esrc = min(ebase + et, n_edges - 1);
        const float4* b4 = reinterpret_cast<const float4*>(bond)
                         + (size_t)esrc * 4 + hcol * 2;
        const float4 f0 = b4[0];
        const float4 f1 = b4[1];
        float bf[8] = {f0.x, f0.y, f0.z, f0.w, f1.x, f1.y, f1.z, f1.w};
        __half* bb = reinterpret_cast<__half*>(bbuf[w][tl]);
        const int r = et & 7;
        const int hi = et >> 3;
        #pragma unroll
        for (int c = 0; c < 8; ++c) {
            const int s = hcol * 8 + c;
            bb[(s * 8 + r) * 2 + hi] = __float2half_rn(bf[c]);
        }
    }
    __syncwarp();

    // ---- per-thread edges / A fragments (ONE uint2 load per edge row) ----
    int dst0[2], dst1[2];
    __half2 hal0[2], hah0[2], hal1[2], hah1[2];
    #pragma unroll
    for (int tl = 0; tl < 2; ++tl) {
        const int ebase = warp_base + tl * 16;
        const int e0 = min(ebase + g, n_edges - 1);
        const int e1 = min(ebase + g + 8, n_edges - 1);
        const int2 p0 = reinterpret_cast<const int2*>(pairs)[e0];
        const int2 p1 = reinterpret_cast<const int2*>(pairs)[e1];
        dst0[tl] = p0.x;
        dst1[tl] = p1.x;
        // fp16 row fragment: j = 4t..4t+3 (sigma layout), 8B contiguous
        const uint2 a0u = *reinterpret_cast<const uint2*>(
            g_Ah + (size_t)p0.y * 16 + 4 * t);
        const uint2 a1u = *reinterpret_cast<const uint2*>(
            g_Ah + (size_t)p1.y * 16 + 4 * t);
        hal0[tl] = *reinterpret_cast<const __half2*>(&a0u.x);
        hah0[tl] = *reinterpret_cast<const __half2*>(&a0u.y);
        hal1[tl] = *reinterpret_cast<const __half2*>(&a1u.x);
        hah1[tl] = *reinterpret_cast<const __half2*>(&a1u.y);
    }

    float d[2][8];
    #pragma unroll
    for (int tl = 0; tl < 2; ++tl)
        #pragma unroll
        for (int q = 0; q < 8; ++q) d[tl][q] = 0.f;

    #pragma unroll
    for (int s = 0; s < 17; ++s) {
        // ONE LDS.128: all 4 B-fragments for this lane (conflict-free phases)
        const uint4 wv = Wsm4[s * 32 + lane];

        #pragma unroll
        for (int tl = 0; tl < 2; ++tl) {
            __half2 bl, bh;
            if (s < 16) {
                const __half2 b2 = bbuf[w][tl][s][g];  // (b[e0][s], b[e1][s])
                bl = __half2half2(__low2half(b2));
                bh = __half2half2(__high2half(b2));
            } else {
                bl = __floats2half2_rn(1.f, 1.f);      // bias row
                bh = bl;
            }
            const unsigned a0 = hmul2u(bl, hal0[tl]);  // row g,   j 4t..4t+1
            const unsigned a1 = hmul2u(bh, hal1[tl]);  // row g+8, j 4t..4t+1
            const unsigned a2 = hmul2u(bl, hah0[tl]);  // row g,   j 4t+2..4t+3
            const unsigned a3 = hmul2u(bh, hah1[tl]);  // row g+8, j 4t+2..4t+3

            mma16816(d[tl][0], d[tl][1], d[tl][2], d[tl][3],
                     a0, a1, a2, a3, wv.x, wv.y);
            mma16816(d[tl][4], d[tl][5], d[tl][6], d[tl][7],
                     a0, a1, a2, a3, wv.z, wv.w);
        }
    }

    // ---- epilogue ----
    #pragma unroll
    for (int tl = 0; tl < 2; ++tl) {
        const int ebase = warp_base + tl * 16;
        const int e0 = ebase + g;
        const int e1 = ebase + g + 8;
        if (e0 < n_edges) {
            float* o = out + (size_t)dst0[tl] * 16;
            red_add_v2(o + 2 * t, d[tl][0], d[tl][1]);
            red_add_v2(o + 8 + 2 * t, d[tl][4], d[tl][5]);
        }
        if (e1 < n_edges) {
            float* o = out + (size_t)dst1[tl] * 16;
            red_add_v2(o + 2 * t, d[tl][2], d[tl][3]);
            red_add_v2(o + 8 + 2 * t, d[tl][6], d[tl][7]);
        }
    }
}

extern "C" void kernel_launch(void* const* d_in, const int* in_sizes, int n_in,
                              void* d_out, int out_size) {
    const float* A     = (const float*)d_in[0];  // atom_features [n_atoms,16]
    const float* bond  = (const float*)d_in[1];  // bond_features [n_edges,16]
    const int*   pairs = (const int*)  d_in[2];  // pair_indices  [n_edges,2]
    const float* Kmat  = (const float*)d_in[3];  // kernel [16,256]
    const float* bias  = (const float*)d_in[4];  // bias [256]
    float* out = (float*)d_out;                  // [n_atoms,16]

    const int n_atoms = in_sizes[0] / 16;
    const int n_edges = in_sizes[2] / 2;
    const int n_out4 = out_size / 4;
    const int n_ah8 = (n_atoms * 16) / 8;

    const int nsetup = max(n_out4, n_ah8);
    setup_kernel<<<(nsetup + 255) / 256, 256>>>(A, Kmat, bias, out,
                                                n_out4, n_ah8);

    const int blocks = (n_edges + EPC - 1) / EPC;
    edge_hmma<<<blocks, NW * 32>>>(bond, pairs, out, n_edges);
}

// round 17
// speedup vs baseline: 1.8323x; 1.1063x over previous
#include <cuda_runtime.h>
#include <cuda_fp16.h>
#include <cstdint>

// EdgeNetwork as warp-level HMMA GEMM (mma.sync.m16n8k16):
//   msg[e,i] = sum_{K} C[e,K] * W[K,i],  K-inner dim 272 (17 steps of 16)
//   C[e, s*16+j] = b'[e,s] * A[nb_e, j],  b' = [b[e], 1.0]
// sigma (K-inner permutation): lane t owns j in {4t..4t+3}; A row-fragment is
// ONE uint2 load of pre-converted fp16.
// pi (output-column permutation): first mma col c -> i = 2c-(c&1), second mma
// -> +2, so lane t owns the contiguous quad i = 4t..4t+3 => ONE red.v4 per
// edge-row per lane (4 red.v4 / warp instead of 8 red.v2).

#define MAX_ATOMS 20000
#define NW 8                  // warps per CTA
#define EPC (NW * 32)         // 256 edges per CTA

__device__ uint4  g_Wu4[17 * 32];          // packed W frags [s*32 + lane]
__device__ __half g_Ah[MAX_ATOMS * 16];    // fp16 atom features

__device__ __forceinline__ void red_add_v4(float* addr, float x, float y,
                                           float z, float w) {
    asm volatile("red.global.add.v4.f32 [%0], {%1,%2,%3,%4};"
                 :: "l"(addr), "f"(x), "f"(y), "f"(z), "f"(w) : "memory");
}

__device__ __forceinline__ unsigned hmul2u(__half2 a, __half2 b) {
    __half2 r = __hmul2(a, b);
    return *reinterpret_cast<unsigned*>(&r);
}

__device__ __forceinline__ void mma16816(float& d0, float& d1, float& d2,
                                         float& d3, unsigned a0, unsigned a1,
                                         unsigned a2, unsigned a3,
                                         unsigned b0, unsigned b1) {
    asm volatile(
        "mma.sync.aligned.m16n8k16.row.col.f32.f16.f16.f32 "
        "{%0,%1,%2,%3}, {%4,%5,%6,%7}, {%8,%9}, {%0,%1,%2,%3};"
        : "+f"(d0), "+f"(d1), "+f"(d2), "+f"(d3)
        : "r"(a0), "r"(a1), "r"(a2), "r"(a3), "r"(b0), "r"(b1));
}

// ------- setup: zero out, convert A->fp16, block 0 builds permuted W frags --
__global__ void setup_kernel(const float* __restrict__ A,
                             const float* __restrict__ Kmat,
                             const float* __restrict__ bias,
                             float* __restrict__ out,
                             int n_out4, int n_ah8) {
    const int gid = blockIdx.x * blockDim.x + threadIdx.x;
    if (gid < n_out4)
        reinterpret_cast<float4*>(out)[gid] = make_float4(0.f, 0.f, 0.f, 0.f);

    if (gid < n_ah8) {   // convert 8 floats -> 8 halfs (one uint4 store)
        const float4 f0 = reinterpret_cast<const float4*>(A)[gid * 2];
        const float4 f1 = reinterpret_cast<const float4*>(A)[gid * 2 + 1];
        __half2 h0 = __floats2half2_rn(f0.x, f0.y);
        __half2 h1 = __floats2half2_rn(f0.z, f0.w);
        __half2 h2 = __floats2half2_rn(f1.x, f1.y);
        __half2 h3 = __floats2half2_rn(f1.z, f1.w);
        uint4 v;
        v.x = *reinterpret_cast<unsigned*>(&h0);
        v.y = *reinterpret_cast<unsigned*>(&h1);
        v.z = *reinterpret_cast<unsigned*>(&h2);
        v.w = *reinterpret_cast<unsigned*>(&h3);
        reinterpret_cast<uint4*>(g_Ah)[gid] = v;
    }

    if (blockIdx.x == 0) {
        const int tid = threadIdx.x;  // 256
        for (int idx = tid; idx < 17 * 32; idx += 256) {
            const int s = idx >> 5;
            const int l = idx & 31;
            const int g = l >> 2;
            const int t = l & 3;
            // W at inner position s*16+j for output column i
            auto wt = [&](int i, int j) -> float {
                return (s < 16) ? Kmat[s * 256 + i * 16 + j]
                                : bias[i * 16 + j];
            };
            // pi: B column slot g of mma0 holds physical i0; mma1 holds i1
            const int i0 = 2 * g - (g & 1);
            const int i1 = i0 + 2;
            // sigma: lane t's mma k-positions map to j = 4t..4t+3
            __half2 x  = __floats2half2_rn(wt(i0, 4*t),     wt(i0, 4*t + 1));
            __half2 y  = __floats2half2_rn(wt(i0, 4*t + 2), wt(i0, 4*t + 3));
            __half2 z  = __floats2half2_rn(wt(i1, 4*t),     wt(i1, 4*t + 1));
            __half2 ww = __floats2half2_rn(wt(i1, 4*t + 2), wt(i1, 4*t + 3));
            uint4 v;
            v.x = *reinterpret_cast<unsigned*>(&x);
            v.y = *reinterpret_cast<unsigned*>(&y);
            v.z = *reinterpret_cast<unsigned*>(&z);
            v.w = *reinterpret_cast<unsigned*>(&ww);
            g_Wu4[idx] = v;
        }
    }
}

// ---------------- main edge kernel -------------------------------------------
__global__ void __launch_bounds__(NW * 32, 5)
edge_hmma(const float* __restrict__ bond,
          const int* __restrict__ pairs,
          float* __restrict__ out,
          int n_edges) {
    __shared__ uint4 Wsm4[17 * 32];             // 8704 B, [s*32 + lane]
    __shared__ __half2 bbuf[NW][2][16][8];      // 8 KB

    const int tid = threadIdx.x;
    const int lane = tid & 31;
    const int w = tid >> 5;
    const int g = lane >> 2;      // fragment row group (0..7)
    const int t = lane & 3;       // fragment quad (0..3)

    // stage packed W fragments (verbatim uint4 copy)
    for (int i = tid; i < 17 * 32; i += NW * 32) Wsm4[i] = g_Wu4[i];
    __syncthreads();

    const int warp_base = blockIdx.x * EPC + w * 32;

    // ---- stage bond rows for both tiles ----
    #pragma unroll
    for (int tl = 0; tl < 2; ++tl) {
        const int ebase = warp_base + tl * 16;
        const int et = lane >> 1;
        const int hcol = lane & 1;          // 0 -> s 0..7, 1 -> s 8..15
        const int esrc = min(ebase + et, n_edges - 1);
        const float4* b4 = reinterpret_cast<const float4*>(bond)
                         + (size_t)esrc * 4 + hcol * 2;
        const float4 f0 = b4[0];
        const float4 f1 = b4[1];
        float bf[8] = {f0.x, f0.y, f0.z, f0.w, f1.x, f1.y, f1.z, f1.w};
        __half* bb = reinterpret_cast<__half*>(bbuf[w][tl]);
        const int r = et & 7;
        const int hi = et >> 3;
        #pragma unroll
        for (int c = 0; c < 8; ++c) {
            const int s = hcol * 8 + c;
            bb[(s * 8 + r) * 2 + hi] = __float2half_rn(bf[c]);
        }
    }
    __syncwarp();

    // ---- per-thread edges / A fragments (ONE uint2 load per edge row) ----
    int dst0[2], dst1[2];
    __half2 hal0[2], hah0[2], hal1[2], hah1[2];
    #pragma unroll
    for (int tl = 0; tl < 2; ++tl) {
        const int ebase = warp_base + tl * 16;
        const int e0 = min(ebase + g, n_edges - 1);
        const int e1 = min(ebase + g + 8, n_edges - 1);
        const int2 p0 = reinterpret_cast<const int2*>(pairs)[e0];
        const int2 p1 = reinterpret_cast<const int2*>(pairs)[e1];
        dst0[tl] = p0.x;
        dst1[tl] = p1.x;
        // fp16 row fragment: j = 4t..4t+3 (sigma layout), 8B contiguous
        const uint2 a0u = *reinterpret_cast<const uint2*>(
            g_Ah + (size_t)p0.y * 16 + 4 * t);
        const uint2 a1u = *reinterpret_cast<const uint2*>(
            g_Ah + (size_t)p1.y * 16 + 4 * t);
        hal0[tl] = *reinterpret_cast<const __half2*>(&a0u.x);
        hah0[tl] = *reinterpret_cast<const __half2*>(&a0u.y);
        hal1[tl] = *reinterpret_cast<const __half2*>(&a1u.x);
        hah1[tl] = *reinterpret_cast<const __half2*>(&a1u.y);
    }

    float d[2][8];
    #pragma unroll
    for (int tl = 0; tl < 2; ++tl)
        #pragma unroll
        for (int q = 0; q < 8; ++q) d[tl][q] = 0.f;

    #pragma unroll
    for (int s = 0; s < 17; ++s) {
        // ONE LDS.128: all 4 B-fragments for this lane (conflict-free phases)
        const uint4 wv = Wsm4[s * 32 + lane];

        #pragma unroll
        for (int tl = 0; tl < 2; ++tl) {
            __half2 bl, bh;
            if (s < 16) {
                const __half2 b2 = bbuf[w][tl][s][g];  // (b[e0][s], b[e1][s])
                bl = __half2half2(__low2half(b2));
                bh = __half2half2(__high2half(b2));
            } else {
                bl = __floats2half2_rn(1.f, 1.f);      // bias row
                bh = bl;
            }
            const unsigned a0 = hmul2u(bl, hal0[tl]);  // row g,   j 4t..4t+1
            const unsigned a1 = hmul2u(bh, hal1[tl]);  // row g+8, j 4t..4t+1
            const unsigned a2 = hmul2u(bl, hah0[tl]);  // row g,   j 4t+2..4t+3
            const unsigned a3 = hmul2u(bh, hah1[tl]);  // row g+8, j 4t+2..4t+3

            mma16816(d[tl][0], d[tl][1], d[tl][2], d[tl][3],
                     a0, a1, a2, a3, wv.x, wv.y);
            mma16816(d[tl][4], d[tl][5], d[tl][6], d[tl][7],
                     a0, a1, a2, a3, wv.z, wv.w);
        }
    }

    // ---- epilogue: pi layout => lane t owns i = 4t..4t+3 contiguously ----
    #pragma unroll
    for (int tl = 0; tl < 2; ++tl) {
        const int ebase = warp_base + tl * 16;
        const int e0 = ebase + g;
        const int e1 = ebase + g + 8;
        if (e0 < n_edges) {
            red_add_v4(out + (size_t)dst0[tl] * 16 + 4 * t,
                       d[tl][0], d[tl][1], d[tl][4], d[tl][5]);
        }
        if (e1 < n_edges) {
            red_add_v4(out + (size_t)dst1[tl] * 16 + 4 * t,
                       d[tl][2], d[tl][3], d[tl][6], d[tl][7]);
        }
    }
}

extern "C" void kernel_launch(void* const* d_in, const int* in_sizes, int n_in,
                              void* d_out, int out_size) {
    const float* A     = (const float*)d_in[0];  // atom_features [n_atoms,16]
    const float* bond  = (const float*)d_in[1];  // bond_features [n_edges,16]
    const int*   pairs = (const int*)  d_in[2];  // pair_indices  [n_edges,2]
    const float* Kmat  = (const float*)d_in[3];  // kernel [16,256]
    const float* bias  = (const float*)d_in[4];  // bias [256]
    float* out = (float*)d_out;                  // [n_atoms,16]

    const int n_atoms = in_sizes[0] / 16;
    const int n_edges = in_sizes[2] / 2;
    const int n_out4 = out_size / 4;
    const int n_ah8 = (n_atoms * 16) / 8;

    const int nsetup = max(n_out4, n_ah8);
    setup_kernel<<<(nsetup + 255) / 256, 256>>>(A, Kmat, bias, out,
                                                n_out4, n_ah8);

    const int blocks = (n_edges + EPC - 1) / EPC;
    edge_hmma<<<blocks, NW * 32>>>(bond, pairs, out, n_edges);
}